// round 5
// baseline (speedup 1.0000x reference)
#include <cuda_runtime.h>
#include <math.h>
#include <stdint.h>

// Problem constants
#define L_SEQ 2048
#define B_SZ  32
#define DIN   128
#define DST   512

// Scratch (device globals per allocation rules)
__device__ float g_pre[L_SEQ * B_SZ * DST];   // [l][b][h]   128 MB
__device__ float g_hs [L_SEQ * B_SZ * DST];   // [l][b][h]   128 MB
__device__ float g_xT [L_SEQ * B_SZ * DIN];   // [l][b][d]    32 MB

union F4U  { float4 f4; ulonglong2 u2; };
union U64F { unsigned long long u; float2 f; };

__device__ __forceinline__ void ffma2(unsigned long long& acc,
                                      unsigned long long a,
                                      unsigned long long b) {
    asm volatile("fma.rn.f32x2 %0, %1, %2, %0;" : "+l"(acc) : "l"(a), "l"(b));
}

__device__ __forceinline__ uint32_t smem_u32(const void* p) {
    return (uint32_t)__cvta_generic_to_shared(p);
}

__device__ __forceinline__ void mbar_wait_cluster(uint32_t addr, uint32_t parity) {
    asm volatile(
        "{\n\t"
        ".reg .pred P;\n\t"
        "WAIT%=:\n\t"
        "mbarrier.try_wait.parity.acquire.cluster.shared::cta.b64 P, [%0], %1, 0x989680;\n\t"
        "@P bra DONE%=;\n\t"
        "bra WAIT%=;\n\t"
        "DONE%=:\n\t"
        "}\n"
        :: "r"(addr), "r"(parity) : "memory");
}

// ---------------------------------------------------------------------------
// Kernel 0: transpose x[b][d][l] -> xT[l][b*128+d].  Tiled 32x32, coalesced.
// ---------------------------------------------------------------------------
__global__ void __launch_bounds__(256) k_xT(const float* __restrict__ x) {
    __shared__ float sm[32 * 33];
    const int l0  = blockIdx.x * 32;
    const int bd0 = blockIdx.y * 32;
    const int t   = threadIdx.x;
    for (int i = t; i < 1024; i += 256) {
        int r = i >> 5, c = i & 31;
        sm[r * 33 + c] = x[(size_t)(bd0 + r) * L_SEQ + l0 + c];
    }
    __syncthreads();
    for (int i = t; i < 1024; i += 256) {
        int r = i >> 5, c = i & 31;
        g_xT[(size_t)(l0 + r) * (B_SZ * DIN) + bd0 + c] = sm[c * 33 + r];
    }
}

// ---------------------------------------------------------------------------
// Kernel 1: pre[l][b][h] = b_ih[h]+b_hh[h] + sum_d xT[l][b][d] * W_ih[h][d]
// ---------------------------------------------------------------------------
#define PRE_SMEM ((128 * 257 + 128 * 36) * 4)

__global__ void __launch_bounds__(512) k_pre(const float* __restrict__ Wih,
                                             const float* __restrict__ bih,
                                             const float* __restrict__ bhh) {
    extern __shared__ float sm[];
    float* w_s = sm;               // [128 d][257]
    float* x_s = sm + 128 * 257;   // [128 d][36]

    const int l  = blockIdx.x;
    const int h0 = blockIdx.y * 256;
    const int t  = threadIdx.x;

    for (int idx = t; idx < 256 * 128; idx += 512) {
        int d = idx & 127, hh = idx >> 7;
        w_s[d * 257 + hh] = Wih[(size_t)(h0 + hh) * DIN + d];
    }
    for (int idx = t; idx < B_SZ * DIN; idx += 512) {
        int d = idx & 127, b = idx >> 7;
        x_s[d * 36 + b] = g_xT[(size_t)l * (B_SZ * DIN) + b * DIN + d];
    }
    __syncthreads();

    const int tx = t & 63;
    const int b0 = (t >> 6) * 4;

    unsigned long long acc[2][4];
#pragma unroll
    for (int m = 0; m < 2; m++)
#pragma unroll
        for (int b = 0; b < 4; b++) acc[m][b] = 0ull;

#pragma unroll 4
    for (int k = 0; k < 128; k++) {
        const float* wr = w_s + k * 257 + tx;
        U64F p0, p1;
        p0.f.x = wr[0];   p0.f.y = wr[64];
        p1.f.x = wr[128]; p1.f.y = wr[192];
        F4U xv; xv.f4 = *(const float4*)(x_s + k * 36 + b0);
        float xs[4] = {xv.f4.x, xv.f4.y, xv.f4.z, xv.f4.w};
#pragma unroll
        for (int b = 0; b < 4; b++) {
            U64F d2; d2.f.x = xs[b]; d2.f.y = xs[b];
            ffma2(acc[0][b], p0.u, d2.u);
            ffma2(acc[1][b], p1.u, d2.u);
        }
    }

    float bias[4];
#pragma unroll
    for (int j = 0; j < 4; j++)
        bias[j] = bih[h0 + tx + 64 * j] + bhh[h0 + tx + 64 * j];

#pragma unroll
    for (int b = 0; b < 4; b++) {
        float* pr = g_pre + ((size_t)l * B_SZ + b0 + b) * DST + h0 + tx;
        U64F u0, u1; u0.u = acc[0][b]; u1.u = acc[1][b];
        pr[0]   = u0.f.x + bias[0];
        pr[64]  = u0.f.y + bias[1];
        pr[128] = u1.f.x + bias[2];
        pr[192] = u1.f.y + bias[3];
    }
}

// ---------------------------------------------------------------------------
// Kernel 2: recurrent scan, warp-autonomous. 16 clusters x 8 CTAs x 512 thr.
// Warp w owns rows [rank*64 + 4w, +4) x 2 batches = 8 full outputs.
// Lane j holds W for K-seg [16j,16j+16) of those 4 rows (64 regs).
// Full reduction in registers via dimension-folding butterfly (output o ends
// on lane o). Each warp pushes its outputs to all 8 peer CTAs the moment it
// finishes; one __syncthreads then 8 remote release-arrives per step.
// ---------------------------------------------------------------------------
__global__ void __launch_bounds__(512, 1) __cluster_dims__(8, 1, 1)
k_rnn(const float* __restrict__ Whh) {
    __shared__ float hbuf[2][2 * DST];   // double-buffered full h, 2 batches
    __shared__ __align__(8) unsigned long long barr[2];

    const int t    = threadIdx.x;
    const int warp = t >> 5;
    const int lane = t & 31;
    uint32_t rank;
    asm("mov.u32 %0, %%cluster_ctarank;" : "=r"(rank));
    const int cl   = blockIdx.x >> 3;    // cluster id 0..15
    const int row0 = (int)rank * 64 + warp * 4;   // first of my 4 rows (global h idx)

    // Weights: 4 rows x 16 K-floats per lane = 16 float4 = 64 regs
    F4U w[4][4];
#pragma unroll
    for (int i = 0; i < 4; i++) {
        const float4* wp = (const float4*)(Whh + (size_t)(row0 + i) * DST + lane * 16);
#pragma unroll
        for (int k = 0; k < 4; k++) w[i][k].f4 = wp[k];
    }

    // h_{-1} = 0 lives in buffer 1
    for (int i = t; i < 2 * DST; i += 512) hbuf[1][i] = 0.f;

    uint32_t bar0 = smem_u32(&barr[0]);
    if (t == 0) {
        asm volatile("mbarrier.init.shared.b64 [%0], %1;" :: "r"(bar0), "r"(8u) : "memory");
        asm volatile("mbarrier.init.shared.b64 [%0], %1;" :: "r"(bar0 + 8), "r"(8u) : "memory");
        asm volatile("fence.mbarrier_init.release.cluster;" ::: "memory");
    }
    __syncthreads();
    asm volatile("barrier.cluster.arrive.aligned;" ::: "memory");
    asm volatile("barrier.cluster.wait.aligned;" ::: "memory");

    const uint32_t hbase = smem_u32(&hbuf[0][0]);
    uint32_t mybar = 0;
    if (t < 8)
        asm("mapa.shared::cluster.u32 %0, %1, %2;" : "=r"(mybar) : "r"(bar0), "r"(t));

    // Output owned by lanes 0-7: o = lane, row = row0 + (o>>1), batch = o&1
    const int ob   = cl * 2 + (lane & 1);
    const int orow = row0 + ((lane >> 1) & 3);
    const size_t outidx = (size_t)ob * DST + orow;

    for (int l = 0; l < L_SEQ; l++) {
        const int cur = l & 1, prev = cur ^ 1;

        float pv = 0.f;
        if (lane < 8) pv = __ldg(g_pre + (size_t)l * (B_SZ * DST) + outidx);

        if (l > 0) mbar_wait_cluster(bar0 + 8u * (uint32_t)prev, ((l - 1) >> 1) & 1);

        // Full partial dots: 4 rows x 2 batches, K-seg [16*lane, +16)
        const float* hbp = hbuf[prev];
        unsigned long long acc[4][2];
#pragma unroll
        for (int i = 0; i < 4; i++) { acc[i][0] = 0ull; acc[i][1] = 0ull; }
#pragma unroll
        for (int b = 0; b < 2; b++) {
            const float4* hp = (const float4*)(hbp + b * DST + lane * 16);
#pragma unroll
            for (int k = 0; k < 4; k++) {
                F4U hv; hv.f4 = hp[k];
#pragma unroll
                for (int i = 0; i < 4; i++) {
                    ffma2(acc[i][b], hv.u2.x, w[i][k].u2.x);
                    ffma2(acc[i][b], hv.u2.y, w[i][k].u2.y);
                }
            }
        }
        // fold f32x2 -> 8 scalars s_o, o = i*2 + b
        float s0, s1, s2, s3, s4, s5, s6, s7;
        {
            U64F u;
            u.u = acc[0][0]; s0 = u.f.x + u.f.y;
            u.u = acc[0][1]; s1 = u.f.x + u.f.y;
            u.u = acc[1][0]; s2 = u.f.x + u.f.y;
            u.u = acc[1][1]; s3 = u.f.x + u.f.y;
            u.u = acc[2][0]; s4 = u.f.x + u.f.y;
            u.u = acc[2][1]; s5 = u.f.x + u.f.y;
            u.u = acc[3][0]; s6 = u.f.x + u.f.y;
            u.u = acc[3][1]; s7 = u.f.x + u.f.y;
        }
        // Butterfly stages 16, 8 on all outputs
#pragma unroll
        for (int st = 16; st >= 8; st >>= 1) {
            s0 += __shfl_xor_sync(0xffffffffu, s0, st);
            s1 += __shfl_xor_sync(0xffffffffu, s1, st);
            s2 += __shfl_xor_sync(0xffffffffu, s2, st);
            s3 += __shfl_xor_sync(0xffffffffu, s3, st);
            s4 += __shfl_xor_sync(0xffffffffu, s4, st);
            s5 += __shfl_xor_sync(0xffffffffu, s5, st);
            s6 += __shfl_xor_sync(0xffffffffu, s6, st);
            s7 += __shfl_xor_sync(0xffffffffu, s7, st);
        }
        // Dimension-folding stages: st=4 (o bit2), st=2 (o bit1), st=1 (o bit0)
        bool p4 = (lane & 4) != 0, p2 = (lane & 2) != 0, p1 = (lane & 1) != 0;
        float k0 = p4 ? s4 : s0, d0 = p4 ? s0 : s4;
        float k1 = p4 ? s5 : s1, d1 = p4 ? s1 : s5;
        float k2 = p4 ? s6 : s2, d2 = p4 ? s2 : s6;
        float k3 = p4 ? s7 : s3, d3 = p4 ? s3 : s7;
        k0 += __shfl_xor_sync(0xffffffffu, d0, 4);
        k1 += __shfl_xor_sync(0xffffffffu, d1, 4);
        k2 += __shfl_xor_sync(0xffffffffu, d2, 4);
        k3 += __shfl_xor_sync(0xffffffffu, d3, 4);
        float m0 = p2 ? k2 : k0, e0 = p2 ? k0 : k2;
        float m1 = p2 ? k3 : k1, e1 = p2 ? k1 : k3;
        m0 += __shfl_xor_sync(0xffffffffu, e0, 2);
        m1 += __shfl_xor_sync(0xffffffffu, e1, 2);
        float f  = p1 ? m1 : m0, ed = p1 ? m0 : m1;
        f += __shfl_xor_sync(0xffffffffu, ed, 1);
        // lane (l&7) now holds the full sum for output o = lane&7

        if (lane < 8) {
            float hv = tanhf(f + pv);
            g_hs[(size_t)l * (B_SZ * DST) + outidx] = hv;
            if (l < L_SEQ - 1) {
                uint32_t off = (uint32_t)((cur * 2 * DST + (lane & 1) * DST + orow) * 4);
#pragma unroll
                for (int p = 0; p < 8; p++) {
                    uint32_t ra;
                    asm("mapa.shared::cluster.u32 %0, %1, %2;"
                        : "=r"(ra) : "r"(hbase + off), "r"(p));
                    asm volatile("st.shared::cluster.f32 [%0], %1;"
                                 :: "r"(ra), "f"(hv) : "memory");
                }
            }
        }
        __syncthreads();

        if (l < L_SEQ - 1 && t < 8)
            asm volatile("mbarrier.arrive.release.cluster.shared::cluster.b64 _, [%0];"
                         :: "r"(mybar + 8u * (uint32_t)cur) : "memory");
    }

    // No CTA may exit while peers could still touch its smem.
    asm volatile("barrier.cluster.arrive.aligned;" ::: "memory");
    asm volatile("barrier.cluster.wait.aligned;" ::: "memory");
}

// ---------------------------------------------------------------------------
// Kernel 3: y[lb][o] = tanh(b_fc[o] + sum_k hs[lb][k] * W_fc[o][k])
// ---------------------------------------------------------------------------
#define OUT_SMEM ((128 * 132 + 128 * 68) * 4)

__global__ void __launch_bounds__(512) k_out(const float* __restrict__ Wfc,
                                             const float* __restrict__ bfc,
                                             float* __restrict__ y) {
    extern __shared__ float sm[];
    float* w_s = sm;               // [128 kk][132]
    float* a_s = sm + 128 * 132;   // [128 kk][68]

    const int t = threadIdx.x;
    const size_t base = (size_t)blockIdx.x * 64;
    const int tx  = t & 31;
    const int lb0 = (t >> 5) * 4;

    unsigned long long acc[2][4];
#pragma unroll
    for (int m = 0; m < 2; m++)
#pragma unroll
        for (int b = 0; b < 4; b++) acc[m][b] = 0ull;

    for (int kc = 0; kc < 4; kc++) {
        __syncthreads();
        for (int idx = t; idx < 128 * 128; idx += 512) {
            int kk = idx & 127, o = idx >> 7;
            w_s[kk * 132 + o] = Wfc[(size_t)o * DST + kc * 128 + kk];
        }
        for (int idx = t; idx < 64 * 128; idx += 512) {
            int kk = idx & 127, row = idx >> 7;
            a_s[kk * 68 + row] = g_hs[(base + row) * DST + kc * 128 + kk];
        }
        __syncthreads();

#pragma unroll 4
        for (int k = 0; k < 128; k++) {
            const float* wr = w_s + k * 132 + tx;
            U64F p0, p1;
            p0.f.x = wr[0];  p0.f.y = wr[32];
            p1.f.x = wr[64]; p1.f.y = wr[96];
            F4U av; av.f4 = *(const float4*)(a_s + k * 68 + lb0);
            float as4[4] = {av.f4.x, av.f4.y, av.f4.z, av.f4.w};
#pragma unroll
            for (int b = 0; b < 4; b++) {
                U64F d2; d2.f.x = as4[b]; d2.f.y = as4[b];
                ffma2(acc[0][b], p0.u, d2.u);
                ffma2(acc[1][b], p1.u, d2.u);
            }
        }
    }

    float bias[4];
#pragma unroll
    for (int j = 0; j < 4; j++) bias[j] = bfc[tx + 32 * j];

#pragma unroll
    for (int b = 0; b < 4; b++) {
        float* yp = y + (base + lb0 + b) * DIN + tx;
        U64F u0, u1; u0.u = acc[0][b]; u1.u = acc[1][b];
        yp[0]  = tanhf(u0.f.x + bias[0]);
        yp[32] = tanhf(u0.f.y + bias[1]);
        yp[64] = tanhf(u1.f.x + bias[2]);
        yp[96] = tanhf(u1.f.y + bias[3]);
    }
}

// ---------------------------------------------------------------------------
extern "C" void kernel_launch(void* const* d_in, const int* in_sizes, int n_in,
                              void* d_out, int out_size) {
    const float* x   = (const float*)d_in[0];
    const float* Wih = (const float*)d_in[1];
    const float* Whh = (const float*)d_in[2];
    const float* bih = (const float*)d_in[3];
    const float* bhh = (const float*)d_in[4];
    const float* Wfc = (const float*)d_in[5];
    const float* bfc = (const float*)d_in[6];
    float* y = (float*)d_out;

    cudaFuncSetAttribute(k_pre, cudaFuncAttributeMaxDynamicSharedMemorySize, PRE_SMEM);
    cudaFuncSetAttribute(k_out, cudaFuncAttributeMaxDynamicSharedMemorySize, OUT_SMEM);

    k_xT<<<dim3(L_SEQ / 32, (B_SZ * DIN) / 32), 256>>>(x);
    k_pre<<<dim3(L_SEQ, 2), 512, PRE_SMEM>>>(Wih, bih, bhh);
    k_rnn<<<128, 512>>>(Whh);
    k_out<<<(L_SEQ * B_SZ) / 64, 512, OUT_SMEM>>>(Wfc, bfc, y);
}

// round 6
// speedup vs baseline: 1.4328x; 1.4328x over previous
#include <cuda_runtime.h>
#include <math.h>
#include <stdint.h>

// Problem constants
#define L_SEQ 2048
#define B_SZ  32
#define DIN   128
#define DST   512

// Scratch (device globals per allocation rules)
__device__ float g_pre[L_SEQ * B_SZ * DST];   // [l][b][h]   128 MB
__device__ float g_hs [L_SEQ * B_SZ * DST];   // [l][b][h]   128 MB
__device__ float g_xT [L_SEQ * B_SZ * DIN];   // [l][b][d]    32 MB

union F4U  { float4 f4; ulonglong2 u2; };
union U64F { unsigned long long u; float2 f; };

__device__ __forceinline__ void ffma2(unsigned long long& acc,
                                      unsigned long long a,
                                      unsigned long long b) {
    asm volatile("fma.rn.f32x2 %0, %1, %2, %0;" : "+l"(acc) : "l"(a), "l"(b));
}

__device__ __forceinline__ uint32_t smem_u32(const void* p) {
    return (uint32_t)__cvta_generic_to_shared(p);
}

__device__ __forceinline__ void mbar_wait_cluster(uint32_t addr, uint32_t parity) {
    asm volatile(
        "{\n\t"
        ".reg .pred P;\n\t"
        "WAIT%=:\n\t"
        "mbarrier.try_wait.parity.acquire.cluster.shared::cta.b64 P, [%0], %1, 0x989680;\n\t"
        "@P bra DONE%=;\n\t"
        "bra WAIT%=;\n\t"
        "DONE%=:\n\t"
        "}\n"
        :: "r"(addr), "r"(parity) : "memory");
}

// ---------------------------------------------------------------------------
// Kernel 0: transpose x[b][d][l] -> xT[l][b*128+d].  Tiled 32x32, coalesced.
// ---------------------------------------------------------------------------
__global__ void __launch_bounds__(256) k_xT(const float* __restrict__ x) {
    __shared__ float sm[32 * 33];
    const int l0  = blockIdx.x * 32;
    const int bd0 = blockIdx.y * 32;
    const int t   = threadIdx.x;
    for (int i = t; i < 1024; i += 256) {
        int r = i >> 5, c = i & 31;
        sm[r * 33 + c] = x[(size_t)(bd0 + r) * L_SEQ + l0 + c];
    }
    __syncthreads();
    for (int i = t; i < 1024; i += 256) {
        int r = i >> 5, c = i & 31;
        g_xT[(size_t)(l0 + r) * (B_SZ * DIN) + bd0 + c] = sm[c * 33 + r];
    }
}

// ---------------------------------------------------------------------------
// Kernel 1: pre[l][b][h] = b_ih[h]+b_hh[h] + sum_d xT[l][b][d] * W_ih[h][d]
// ---------------------------------------------------------------------------
#define PRE_SMEM ((128 * 257 + 128 * 36) * 4)

__global__ void __launch_bounds__(512) k_pre(const float* __restrict__ Wih,
                                             const float* __restrict__ bih,
                                             const float* __restrict__ bhh) {
    extern __shared__ float sm[];
    float* w_s = sm;               // [128 d][257]
    float* x_s = sm + 128 * 257;   // [128 d][36]

    const int l  = blockIdx.x;
    const int h0 = blockIdx.y * 256;
    const int t  = threadIdx.x;

    for (int idx = t; idx < 256 * 128; idx += 512) {
        int d = idx & 127, hh = idx >> 7;
        w_s[d * 257 + hh] = Wih[(size_t)(h0 + hh) * DIN + d];
    }
    for (int idx = t; idx < B_SZ * DIN; idx += 512) {
        int d = idx & 127, b = idx >> 7;
        x_s[d * 36 + b] = g_xT[(size_t)l * (B_SZ * DIN) + b * DIN + d];
    }
    __syncthreads();

    const int tx = t & 63;
    const int b0 = (t >> 6) * 4;

    unsigned long long acc[2][4];
#pragma unroll
    for (int m = 0; m < 2; m++)
#pragma unroll
        for (int b = 0; b < 4; b++) acc[m][b] = 0ull;

#pragma unroll 4
    for (int k = 0; k < 128; k++) {
        const float* wr = w_s + k * 257 + tx;
        U64F p0, p1;
        p0.f.x = wr[0];   p0.f.y = wr[64];
        p1.f.x = wr[128]; p1.f.y = wr[192];
        F4U xv; xv.f4 = *(const float4*)(x_s + k * 36 + b0);
        float xs[4] = {xv.f4.x, xv.f4.y, xv.f4.z, xv.f4.w};
#pragma unroll
        for (int b = 0; b < 4; b++) {
            U64F d2; d2.f.x = xs[b]; d2.f.y = xs[b];
            ffma2(acc[0][b], p0.u, d2.u);
            ffma2(acc[1][b], p1.u, d2.u);
        }
    }

    float bias[4];
#pragma unroll
    for (int j = 0; j < 4; j++)
        bias[j] = bih[h0 + tx + 64 * j] + bhh[h0 + tx + 64 * j];

#pragma unroll
    for (int b = 0; b < 4; b++) {
        float* pr = g_pre + ((size_t)l * B_SZ + b0 + b) * DST + h0 + tx;
        U64F u0, u1; u0.u = acc[0][b]; u1.u = acc[1][b];
        pr[0]   = u0.f.x + bias[0];
        pr[64]  = u0.f.y + bias[1];
        pr[128] = u1.f.x + bias[2];
        pr[192] = u1.f.y + bias[3];
    }
}

// ---------------------------------------------------------------------------
// Kernel 2: recurrent scan with BROADCAST h-reads. 16 clusters x 8 CTAs x
// 512 threads. Warp (rg,kw) owns rows [32rg,+32) x K [64kw,+64); lane = row,
// so all 32 lanes read the SAME h float4 (smem broadcast, N=1) — kills the
// 32x LDS amplification. W register-resident (64 f/thread). Partials reduced
// by a 4-warp tail; remote arrives after a named barrier of that group only.
// ---------------------------------------------------------------------------
__global__ void __launch_bounds__(512, 1) __cluster_dims__(8, 1, 1)
k_rnn(const float* __restrict__ Whh) {
    __shared__ float hbuf[2][2 * DST];   // double-buffered full h, 2 batches
    __shared__ float red[2][64][9];      // [batch][row][kslice], padded
    __shared__ __align__(8) unsigned long long barr[2];

    const int t    = threadIdx.x;
    const int warp = t >> 5;
    const int lane = t & 31;
    uint32_t rank;
    asm("mov.u32 %0, %%cluster_ctarank;" : "=r"(rank));
    const int cl  = blockIdx.x >> 3;     // cluster id 0..15
    const int rg  = warp & 1;            // row group 0/1
    const int kw  = warp >> 1;           // K-slice 0..7 (64 wide)
    const int row = rg * 32 + lane;      // local row 0..63
    const int ks  = kw * 64;

    // W: row (rank*64+row), K [ks, ks+64) -> 16 float4 in registers
    F4U w[16];
    {
        const float4* wp = (const float4*)(Whh + (size_t)(rank * 64 + row) * DST + ks);
#pragma unroll
        for (int i = 0; i < 16; i++) w[i].f4 = wp[i];
    }

    // h_{-1} = 0 lives in buffer 1
    for (int i = t; i < 2 * DST; i += 512) hbuf[1][i] = 0.f;

    uint32_t bar0 = smem_u32(&barr[0]);
    if (t == 0) {
        asm volatile("mbarrier.init.shared.b64 [%0], %1;" :: "r"(bar0), "r"(8u) : "memory");
        asm volatile("mbarrier.init.shared.b64 [%0], %1;" :: "r"(bar0 + 8), "r"(8u) : "memory");
        asm volatile("fence.mbarrier_init.release.cluster;" ::: "memory");
    }
    __syncthreads();
    asm volatile("barrier.cluster.arrive.aligned;" ::: "memory");
    asm volatile("barrier.cluster.wait.aligned;" ::: "memory");

    const uint32_t hbase = smem_u32(&hbuf[0][0]);
    uint32_t peer_h[8];
#pragma unroll
    for (int p = 0; p < 8; p++)
        asm("mapa.shared::cluster.u32 %0, %1, %2;" : "=r"(peer_h[p]) : "r"(hbase), "r"(p));
    uint32_t mybar = 0;
    if (t < 8)
        asm("mapa.shared::cluster.u32 %0, %1, %2;" : "=r"(mybar) : "r"(bar0), "r"(t));

    // Reduce-group (t<128) constants: batch tb, row tr
    const int tb = t >> 6;
    const int tr = t & 63;
    const size_t outidx = (size_t)(cl * 2 + tb) * DST + rank * 64 + tr;
    const uint32_t pushoff_base = (uint32_t)((tb * DST + (int)rank * 64 + tr) * 4);

    for (int l = 0; l < L_SEQ; l++) {
        const int cur = l & 1, prev = cur ^ 1;

        float pv = 0.f;
        if (t < 128) pv = __ldg(g_pre + (size_t)l * (B_SZ * DST) + outidx);

        if (l > 0) mbar_wait_cluster(bar0 + 8u * (uint32_t)prev, ((l - 1) >> 1) & 1);

        // Partial dots: my row x my K-slice, both batches; h via broadcast LDS
        const float* hbp = hbuf[prev];
#pragma unroll
        for (int b = 0; b < 2; b++) {
            const float4* hp = (const float4*)(hbp + b * DST + ks);
            unsigned long long a0 = 0ull, a1 = 0ull;
#pragma unroll
            for (int i = 0; i < 16; i++) {
                F4U hv; hv.f4 = hp[i];          // all lanes same addr: broadcast
                ffma2(a0, hv.u2.x, w[i].u2.x);
                ffma2(a1, hv.u2.y, w[i].u2.y);
            }
            U64F u0, u1; u0.u = a0; u1.u = a1;
            red[b][row][kw] = u0.f.x + u0.f.y + u1.f.x + u1.f.y;
        }
        __syncthreads();

        if (t < 128) {
            float s = pv;
#pragma unroll
            for (int k2 = 0; k2 < 8; k2++) s += red[tb][tr][k2];
            float hv = tanhf(s);
            g_hs[(size_t)l * (B_SZ * DST) + outidx] = hv;
            if (l < L_SEQ - 1) {
                uint32_t off = (uint32_t)(cur * 2 * DST * 4) + pushoff_base;
#pragma unroll
                for (int p = 0; p < 8; p++)
                    asm volatile("st.shared::cluster.f32 [%0], %1;"
                                 :: "r"(peer_h[p] + off), "f"(hv) : "memory");
                // only the 4 reduce warps need ordering before the arrives
                asm volatile("bar.sync 1, 128;" ::: "memory");
                if (t < 8)
                    asm volatile("mbarrier.arrive.release.cluster.shared::cluster.b64 _, [%0];"
                                 :: "r"(mybar + 8u * (uint32_t)cur) : "memory");
            }
        }
    }

    // No CTA may exit while peers could still touch its smem.
    asm volatile("barrier.cluster.arrive.aligned;" ::: "memory");
    asm volatile("barrier.cluster.wait.aligned;" ::: "memory");
}

// ---------------------------------------------------------------------------
// Kernel 3: y[lb][o] = tanh(b_fc[o] + sum_k hs[lb][k] * W_fc[o][k])
// ---------------------------------------------------------------------------
#define OUT_SMEM ((128 * 132 + 128 * 68) * 4)

__global__ void __launch_bounds__(512) k_out(const float* __restrict__ Wfc,
                                             const float* __restrict__ bfc,
                                             float* __restrict__ y) {
    extern __shared__ float sm[];
    float* w_s = sm;               // [128 kk][132]
    float* a_s = sm + 128 * 132;   // [128 kk][68]

    const int t = threadIdx.x;
    const size_t base = (size_t)blockIdx.x * 64;
    const int tx  = t & 31;
    const int lb0 = (t >> 5) * 4;

    unsigned long long acc[2][4];
#pragma unroll
    for (int m = 0; m < 2; m++)
#pragma unroll
        for (int b = 0; b < 4; b++) acc[m][b] = 0ull;

    for (int kc = 0; kc < 4; kc++) {
        __syncthreads();
        for (int idx = t; idx < 128 * 128; idx += 512) {
            int kk = idx & 127, o = idx >> 7;
            w_s[kk * 132 + o] = Wfc[(size_t)o * DST + kc * 128 + kk];
        }
        for (int idx = t; idx < 64 * 128; idx += 512) {
            int kk = idx & 127, row = idx >> 7;
            a_s[kk * 68 + row] = g_hs[(base + row) * DST + kc * 128 + kk];
        }
        __syncthreads();

#pragma unroll 4
        for (int k = 0; k < 128; k++) {
            const float* wr = w_s + k * 132 + tx;
            U64F p0, p1;
            p0.f.x = wr[0];  p0.f.y = wr[32];
            p1.f.x = wr[64]; p1.f.y = wr[96];
            F4U av; av.f4 = *(const float4*)(a_s + k * 68 + lb0);
            float as4[4] = {av.f4.x, av.f4.y, av.f4.z, av.f4.w};
#pragma unroll
            for (int b = 0; b < 4; b++) {
                U64F d2; d2.f.x = as4[b]; d2.f.y = as4[b];
                ffma2(acc[0][b], p0.u, d2.u);
                ffma2(acc[1][b], p1.u, d2.u);
            }
        }
    }

    float bias[4];
#pragma unroll
    for (int j = 0; j < 4; j++) bias[j] = bfc[tx + 32 * j];

#pragma unroll
    for (int b = 0; b < 4; b++) {
        float* yp = y + (base + lb0 + b) * DIN + tx;
        U64F u0, u1; u0.u = acc[0][b]; u1.u = acc[1][b];
        yp[0]  = tanhf(u0.f.x + bias[0]);
        yp[32] = tanhf(u0.f.y + bias[1]);
        yp[64] = tanhf(u1.f.x + bias[2]);
        yp[96] = tanhf(u1.f.y + bias[3]);
    }
}

// ---------------------------------------------------------------------------
extern "C" void kernel_launch(void* const* d_in, const int* in_sizes, int n_in,
                              void* d_out, int out_size) {
    const float* x   = (const float*)d_in[0];
    const float* Wih = (const float*)d_in[1];
    const float* Whh = (const float*)d_in[2];
    const float* bih = (const float*)d_in[3];
    const float* bhh = (const float*)d_in[4];
    const float* Wfc = (const float*)d_in[5];
    const float* bfc = (const float*)d_in[6];
    float* y = (float*)d_out;

    cudaFuncSetAttribute(k_pre, cudaFuncAttributeMaxDynamicSharedMemorySize, PRE_SMEM);
    cudaFuncSetAttribute(k_out, cudaFuncAttributeMaxDynamicSharedMemorySize, OUT_SMEM);

    k_xT<<<dim3(L_SEQ / 32, (B_SZ * DIN) / 32), 256>>>(x);
    k_pre<<<dim3(L_SEQ, 2), 512, PRE_SMEM>>>(Wih, bih, bhh);
    k_rnn<<<128, 512>>>(Whh);
    k_out<<<(L_SEQ * B_SZ) / 64, 512, OUT_SMEM>>>(Wfc, bfc, y);
}

// round 7
// speedup vs baseline: 1.7043x; 1.1894x over previous
#include <cuda_runtime.h>
#include <math.h>
#include <stdint.h>

// Problem constants
#define L_SEQ 2048
#define B_SZ  32
#define DIN   128
#define DST   512

// Scratch (device globals per allocation rules)
__device__ float g_pre[L_SEQ * B_SZ * DST];   // [l][b][h]   128 MB
__device__ float g_hs [L_SEQ * B_SZ * DST];   // [l][b][h]   128 MB
__device__ float g_xT [L_SEQ * B_SZ * DIN];   // [l][b][d]    32 MB

union F4U  { float4 f4; ulonglong2 u2; };
union U64F { unsigned long long u; float2 f; };

__device__ __forceinline__ void ffma2(unsigned long long& acc,
                                      unsigned long long a,
                                      unsigned long long b) {
    asm volatile("fma.rn.f32x2 %0, %1, %2, %0;" : "+l"(acc) : "l"(a), "l"(b));
}

__device__ __forceinline__ uint32_t smem_u32(const void* p) {
    return (uint32_t)__cvta_generic_to_shared(p);
}

__device__ __forceinline__ void mbar_wait_cluster(uint32_t addr, uint32_t parity) {
    asm volatile(
        "{\n\t"
        ".reg .pred P;\n\t"
        "WAIT%=:\n\t"
        "mbarrier.try_wait.parity.acquire.cluster.shared::cta.b64 P, [%0], %1, 0x989680;\n\t"
        "@P bra DONE%=;\n\t"
        "bra WAIT%=;\n\t"
        "DONE%=:\n\t"
        "}\n"
        :: "r"(addr), "r"(parity) : "memory");
}

// ---------------------------------------------------------------------------
// Kernel 0: transpose x[b][d][l] -> xT[l][b*128+d].  Tiled 32x32, coalesced.
// ---------------------------------------------------------------------------
__global__ void __launch_bounds__(256) k_xT(const float* __restrict__ x) {
    __shared__ float sm[32 * 33];
    const int l0  = blockIdx.x * 32;
    const int bd0 = blockIdx.y * 32;
    const int t   = threadIdx.x;
    for (int i = t; i < 1024; i += 256) {
        int r = i >> 5, c = i & 31;
        sm[r * 33 + c] = x[(size_t)(bd0 + r) * L_SEQ + l0 + c];
    }
    __syncthreads();
    for (int i = t; i < 1024; i += 256) {
        int r = i >> 5, c = i & 31;
        g_xT[(size_t)(l0 + r) * (B_SZ * DIN) + bd0 + c] = sm[c * 33 + r];
    }
}

// ---------------------------------------------------------------------------
// Kernel 1: pre[l][b][h] = b_ih[h]+b_hh[h] + sum_d xT[l][b][d] * W_ih[h][d]
// ---------------------------------------------------------------------------
#define PRE_SMEM ((128 * 257 + 128 * 36) * 4)

__global__ void __launch_bounds__(512) k_pre(const float* __restrict__ Wih,
                                             const float* __restrict__ bih,
                                             const float* __restrict__ bhh) {
    extern __shared__ float sm[];
    float* w_s = sm;               // [128 d][257]
    float* x_s = sm + 128 * 257;   // [128 d][36]

    const int l  = blockIdx.x;
    const int h0 = blockIdx.y * 256;
    const int t  = threadIdx.x;

    for (int idx = t; idx < 256 * 128; idx += 512) {
        int d = idx & 127, hh = idx >> 7;
        w_s[d * 257 + hh] = Wih[(size_t)(h0 + hh) * DIN + d];
    }
    for (int idx = t; idx < B_SZ * DIN; idx += 512) {
        int d = idx & 127, b = idx >> 7;
        x_s[d * 36 + b] = g_xT[(size_t)l * (B_SZ * DIN) + b * DIN + d];
    }
    __syncthreads();

    const int tx = t & 63;
    const int b0 = (t >> 6) * 4;

    unsigned long long acc[2][4];
#pragma unroll
    for (int m = 0; m < 2; m++)
#pragma unroll
        for (int b = 0; b < 4; b++) acc[m][b] = 0ull;

#pragma unroll 4
    for (int k = 0; k < 128; k++) {
        const float* wr = w_s + k * 257 + tx;
        U64F p0, p1;
        p0.f.x = wr[0];   p0.f.y = wr[64];
        p1.f.x = wr[128]; p1.f.y = wr[192];
        F4U xv; xv.f4 = *(const float4*)(x_s + k * 36 + b0);
        float xs[4] = {xv.f4.x, xv.f4.y, xv.f4.z, xv.f4.w};
#pragma unroll
        for (int b = 0; b < 4; b++) {
            U64F d2; d2.f.x = xs[b]; d2.f.y = xs[b];
            ffma2(acc[0][b], p0.u, d2.u);
            ffma2(acc[1][b], p1.u, d2.u);
        }
    }

    float bias[4];
#pragma unroll
    for (int j = 0; j < 4; j++)
        bias[j] = bih[h0 + tx + 64 * j] + bhh[h0 + tx + 64 * j];

#pragma unroll
    for (int b = 0; b < 4; b++) {
        float* pr = g_pre + ((size_t)l * B_SZ + b0 + b) * DST + h0 + tx;
        U64F u0, u1; u0.u = acc[0][b]; u1.u = acc[1][b];
        pr[0]   = u0.f.x + bias[0];
        pr[64]  = u0.f.y + bias[1];
        pr[128] = u1.f.x + bias[2];
        pr[192] = u1.f.y + bias[3];
    }
}

// ---------------------------------------------------------------------------
// Kernel 2: recurrent scan, warp-specialized + per-batch pipelined.
// 16 clusters x 8 CTAs x 640 threads.
//   warps 0-15  (t<512):     compute (broadcast-LDS partials; W in regs)
//   warps 16-17 (512<=t<576): tail for batch 0 (reduce/tanh/push/arrive)
//   warps 18-19 (576<=t<640): tail for batch 1
// Each batch has its own mbarrier pair (double-buffered parity), so batch-0's
// tail + cross-CTA hop overlap batch-1's compute and vice versa.
// ---------------------------------------------------------------------------
__global__ void __launch_bounds__(640, 1) __cluster_dims__(8, 1, 1)
k_rnn(const float* __restrict__ Whh) {
    __shared__ float hbuf[2][2 * DST];   // [parity][batch*512+h] exchange buf
    __shared__ float red[2][64][9];      // [batch][row][kslice], padded
    __shared__ __align__(8) unsigned long long barr[4]; // [batch][slot]

    const int t    = threadIdx.x;
    const int warp = t >> 5;
    const int lane = t & 31;
    uint32_t rank;
    asm("mov.u32 %0, %%cluster_ctarank;" : "=r"(rank));
    const int cl = blockIdx.x >> 3;      // cluster id 0..15

    // ---- compute-warp constants + register W ----
    const int rg  = warp & 1;            // row group
    const int kw  = warp >> 1;           // K slice 0..7
    const int row = rg * 32 + lane;      // local row 0..63
    const int ks  = kw * 64;
    F4U w[16];
    if (t < 512) {
        const float4* wp = (const float4*)(Whh + (size_t)(rank * 64 + row) * DST + ks);
#pragma unroll
        for (int i = 0; i < 16; i++) w[i].f4 = wp[i];
    }

    // h_{-1} = 0 lives in buffer 1
    for (int i = t; i < 2 * DST; i += 640) hbuf[1][i] = 0.f;

    uint32_t bar0 = smem_u32(&barr[0]);
    if (t == 0) {
#pragma unroll
        for (int i = 0; i < 4; i++)
            asm volatile("mbarrier.init.shared.b64 [%0], %1;"
                         :: "r"(bar0 + 8u * i), "r"(8u) : "memory");
        asm volatile("fence.mbarrier_init.release.cluster;" ::: "memory");
    }
    __syncthreads();
    asm volatile("barrier.cluster.arrive.aligned;" ::: "memory");
    asm volatile("barrier.cluster.wait.aligned;" ::: "memory");

    const uint32_t hbase = smem_u32(&hbuf[0][0]);
    uint32_t peer_h[8];
#pragma unroll
    for (int p = 0; p < 8; p++)
        asm("mapa.shared::cluster.u32 %0, %1, %2;" : "=r"(peer_h[p]) : "r"(hbase), "r"(p));

    if (t < 512) {
        // ================= COMPUTE WARPS =================
        for (int l = 0; l < L_SEQ; l++) {
            const int prev = (l & 1) ^ 1;
            const uint32_t wpar = (uint32_t)(((l - 1) >> 1) & 1);
            const uint32_t wslot = (uint32_t)((l - 1) & 1);
            const float* hbp = hbuf[prev];

            // ---- batch 0 ----
            if (l > 0) mbar_wait_cluster(bar0 + 8u * (0u * 2u + wslot), wpar);
            {
                const float4* hp = (const float4*)(hbp + ks);
                unsigned long long a0 = 0ull, a1 = 0ull;
#pragma unroll
                for (int i = 0; i < 16; i++) {
                    F4U hv; hv.f4 = hp[i];      // broadcast LDS
                    ffma2(a0, hv.u2.x, w[i].u2.x);
                    ffma2(a1, hv.u2.y, w[i].u2.y);
                }
                U64F u0, u1; u0.u = a0; u1.u = a1;
                red[0][row][kw] = u0.f.x + u0.f.y + u1.f.x + u1.f.y;
            }
            asm volatile("bar.arrive 1, 576;" ::: "memory");

            // ---- batch 1 ----
            if (l > 0) mbar_wait_cluster(bar0 + 8u * (1u * 2u + wslot), wpar);
            {
                const float4* hp = (const float4*)(hbp + DST + ks);
                unsigned long long a0 = 0ull, a1 = 0ull;
#pragma unroll
                for (int i = 0; i < 16; i++) {
                    F4U hv; hv.f4 = hp[i];
                    ffma2(a0, hv.u2.x, w[i].u2.x);
                    ffma2(a1, hv.u2.y, w[i].u2.y);
                }
                U64F u0, u1; u0.u = a0; u1.u = a1;
                red[1][row][kw] = u0.f.x + u0.f.y + u1.f.x + u1.f.y;
            }
            asm volatile("bar.arrive 2, 576;" ::: "memory");
        }
    } else {
        // ================= TAIL WARPS =================
        const int tb = (t >= 576) ? 1 : 0;          // my batch
        const int u  = (t - 512) & 63;              // my row 0..63
        const int mybarid = 1 + tb;                 // phase barrier (1 or 2)
        const int grpbar  = 3 + tb;                 // group barrier (3 or 4)
        const size_t outidx = (size_t)(cl * 2 + tb) * DST + rank * 64 + u;
        const uint32_t pushoff = (uint32_t)((tb * DST + (int)rank * 64 + u) * 4);
        const uint32_t flagoff = 8u * (uint32_t)(tb * 2);

        for (int l = 0; l < L_SEQ; l++) {
            const int cur = l & 1;
            float pv = __ldg(g_pre + (size_t)l * (B_SZ * DST) + outidx);

            // wait for this batch's partials
            asm volatile("bar.sync %0, 576;" :: "r"(mybarid) : "memory");

            float s = pv;
#pragma unroll
            for (int k2 = 0; k2 < 8; k2++) s += red[tb][u][k2];
            float hv = tanhf(s);
            g_hs[(size_t)l * (B_SZ * DST) + outidx] = hv;

            if (l < L_SEQ - 1) {
                uint32_t off = (uint32_t)(cur * 2 * DST * 4) + pushoff;
#pragma unroll
                for (int p = 0; p < 8; p++)
                    asm volatile("st.shared::cluster.f32 [%0], %1;"
                                 :: "r"(peer_h[p] + off), "f"(hv) : "memory");
                // order this 64-thread group's pushes before the arrives
                asm volatile("bar.sync %0, 64;" :: "r"(grpbar) : "memory");
                if (u < 8) {
                    uint32_t ra;
                    asm("mapa.shared::cluster.u32 %0, %1, %2;"
                        : "=r"(ra) : "r"(bar0 + flagoff + 8u * (uint32_t)cur), "r"(u));
                    asm volatile("mbarrier.arrive.release.cluster.shared::cluster.b64 _, [%0];"
                                 :: "r"(ra) : "memory");
                }
            }
        }
    }

    // No CTA may exit while peers could still touch its smem.
    asm volatile("barrier.cluster.arrive.aligned;" ::: "memory");
    asm volatile("barrier.cluster.wait.aligned;" ::: "memory");
}

// ---------------------------------------------------------------------------
// Kernel 3: y[lb][o] = tanh(b_fc[o] + sum_k hs[lb][k] * W_fc[o][k])
// ---------------------------------------------------------------------------
#define OUT_SMEM ((128 * 132 + 128 * 68) * 4)

__global__ void __launch_bounds__(512) k_out(const float* __restrict__ Wfc,
                                             const float* __restrict__ bfc,
                                             float* __restrict__ y) {
    extern __shared__ float sm[];
    float* w_s = sm;               // [128 kk][132]
    float* a_s = sm + 128 * 132;   // [128 kk][68]

    const int t = threadIdx.x;
    const size_t base = (size_t)blockIdx.x * 64;
    const int tx  = t & 31;
    const int lb0 = (t >> 5) * 4;

    unsigned long long acc[2][4];
#pragma unroll
    for (int m = 0; m < 2; m++)
#pragma unroll
        for (int b = 0; b < 4; b++) acc[m][b] = 0ull;

    for (int kc = 0; kc < 4; kc++) {
        __syncthreads();
        for (int idx = t; idx < 128 * 128; idx += 512) {
            int kk = idx & 127, o = idx >> 7;
            w_s[kk * 132 + o] = Wfc[(size_t)o * DST + kc * 128 + kk];
        }
        for (int idx = t; idx < 64 * 128; idx += 512) {
            int kk = idx & 127, row = idx >> 7;
            a_s[kk * 68 + row] = g_hs[(base + row) * DST + kc * 128 + kk];
        }
        __syncthreads();

#pragma unroll 4
        for (int k = 0; k < 128; k++) {
            const float* wr = w_s + k * 132 + tx;
            U64F p0, p1;
            p0.f.x = wr[0];  p0.f.y = wr[32];
            p1.f.x = wr[64]; p1.f.y = wr[96];
            F4U av; av.f4 = *(const float4*)(a_s + k * 68 + lb0);
            float as4[4] = {av.f4.x, av.f4.y, av.f4.z, av.f4.w};
#pragma unroll
            for (int b = 0; b < 4; b++) {
                U64F d2; d2.f.x = as4[b]; d2.f.y = as4[b];
                ffma2(acc[0][b], p0.u, d2.u);
                ffma2(acc[1][b], p1.u, d2.u);
            }
        }
    }

    float bias[4];
#pragma unroll
    for (int j = 0; j < 4; j++) bias[j] = bfc[tx + 32 * j];

#pragma unroll
    for (int b = 0; b < 4; b++) {
        float* yp = y + (base + lb0 + b) * DIN + tx;
        U64F u0, u1; u0.u = acc[0][b]; u1.u = acc[1][b];
        yp[0]  = tanhf(u0.f.x + bias[0]);
        yp[32] = tanhf(u0.f.y + bias[1]);
        yp[64] = tanhf(u1.f.x + bias[2]);
        yp[96] = tanhf(u1.f.y + bias[3]);
    }
}

// ---------------------------------------------------------------------------
extern "C" void kernel_launch(void* const* d_in, const int* in_sizes, int n_in,
                              void* d_out, int out_size) {
    const float* x   = (const float*)d_in[0];
    const float* Wih = (const float*)d_in[1];
    const float* Whh = (const float*)d_in[2];
    const float* bih = (const float*)d_in[3];
    const float* bhh = (const float*)d_in[4];
    const float* Wfc = (const float*)d_in[5];
    const float* bfc = (const float*)d_in[6];
    float* y = (float*)d_out;

    cudaFuncSetAttribute(k_pre, cudaFuncAttributeMaxDynamicSharedMemorySize, PRE_SMEM);
    cudaFuncSetAttribute(k_out, cudaFuncAttributeMaxDynamicSharedMemorySize, OUT_SMEM);

    k_xT<<<dim3(L_SEQ / 32, (B_SZ * DIN) / 32), 256>>>(x);
    k_pre<<<dim3(L_SEQ, 2), 512, PRE_SMEM>>>(Wih, bih, bhh);
    k_rnn<<<128, 640>>>(Whh);
    k_out<<<(L_SEQ * B_SZ) / 64, 512, OUT_SMEM>>>(Wfc, bfc, y);
}

// round 8
// speedup vs baseline: 2.4929x; 1.4627x over previous
#include <cuda_runtime.h>
#include <math.h>
#include <stdint.h>

// Problem constants
#define L_SEQ 2048
#define B_SZ  32
#define DIN   128
#define DST   512
#define NB4   4      // batches per cluster

// Scratch (device globals per allocation rules)
__device__ float g_pre[L_SEQ * B_SZ * DST];   // [l][b][h]   128 MB
__device__ float g_hs [L_SEQ * B_SZ * DST];   // [l][b][h]   128 MB
__device__ float g_xT [L_SEQ * B_SZ * DIN];   // [l][b][d]    32 MB

union F4U  { float4 f4; ulonglong2 u2; };
union U64F { unsigned long long u; float2 f; };

__device__ __forceinline__ void ffma2(unsigned long long& acc,
                                      unsigned long long a,
                                      unsigned long long b) {
    asm volatile("fma.rn.f32x2 %0, %1, %2, %0;" : "+l"(acc) : "l"(a), "l"(b));
}

__device__ __forceinline__ uint32_t smem_u32(const void* p) {
    return (uint32_t)__cvta_generic_to_shared(p);
}

__device__ __forceinline__ void mbar_wait_cluster(uint32_t addr, uint32_t parity) {
    asm volatile(
        "{\n\t"
        ".reg .pred P;\n\t"
        "WAIT%=:\n\t"
        "mbarrier.try_wait.parity.acquire.cluster.shared::cta.b64 P, [%0], %1, 0x989680;\n\t"
        "@P bra DONE%=;\n\t"
        "bra WAIT%=;\n\t"
        "DONE%=:\n\t"
        "}\n"
        :: "r"(addr), "r"(parity) : "memory");
}

// ---------------------------------------------------------------------------
// Kernel 0: transpose x[b][d][l] -> xT[l][b*128+d].
// ---------------------------------------------------------------------------
__global__ void __launch_bounds__(256) k_xT(const float* __restrict__ x) {
    __shared__ float sm[32 * 33];
    const int l0  = blockIdx.x * 32;
    const int bd0 = blockIdx.y * 32;
    const int t   = threadIdx.x;
    for (int i = t; i < 1024; i += 256) {
        int r = i >> 5, c = i & 31;
        sm[r * 33 + c] = x[(size_t)(bd0 + r) * L_SEQ + l0 + c];
    }
    __syncthreads();
    for (int i = t; i < 1024; i += 256) {
        int r = i >> 5, c = i & 31;
        g_xT[(size_t)(l0 + r) * (B_SZ * DIN) + bd0 + c] = sm[c * 33 + r];
    }
}

// ---------------------------------------------------------------------------
// Kernel 1: pre[l][b][h] = b_ih[h]+b_hh[h] + sum_d xT[l][b][d] * W_ih[h][d]
// ---------------------------------------------------------------------------
#define PRE_SMEM ((128 * 257 + 128 * 36) * 4)

__global__ void __launch_bounds__(512) k_pre(const float* __restrict__ Wih,
                                             const float* __restrict__ bih,
                                             const float* __restrict__ bhh) {
    extern __shared__ float sm[];
    float* w_s = sm;               // [128 d][257]
    float* x_s = sm + 128 * 257;   // [128 d][36]

    const int l  = blockIdx.x;
    const int h0 = blockIdx.y * 256;
    const int t  = threadIdx.x;

    for (int idx = t; idx < 256 * 128; idx += 512) {
        int d = idx & 127, hh = idx >> 7;
        w_s[d * 257 + hh] = Wih[(size_t)(h0 + hh) * DIN + d];
    }
    for (int idx = t; idx < B_SZ * DIN; idx += 512) {
        int d = idx & 127, b = idx >> 7;
        x_s[d * 36 + b] = g_xT[(size_t)l * (B_SZ * DIN) + b * DIN + d];
    }
    __syncthreads();

    const int tx = t & 63;
    const int b0 = (t >> 6) * 4;

    unsigned long long acc[2][4];
#pragma unroll
    for (int m = 0; m < 2; m++)
#pragma unroll
        for (int b = 0; b < 4; b++) acc[m][b] = 0ull;

#pragma unroll 4
    for (int k = 0; k < 128; k++) {
        const float* wr = w_s + k * 257 + tx;
        U64F p0, p1;
        p0.f.x = wr[0];   p0.f.y = wr[64];
        p1.f.x = wr[128]; p1.f.y = wr[192];
        F4U xv; xv.f4 = *(const float4*)(x_s + k * 36 + b0);
        float xs[4] = {xv.f4.x, xv.f4.y, xv.f4.z, xv.f4.w};
#pragma unroll
        for (int b = 0; b < 4; b++) {
            U64F d2; d2.f.x = xs[b]; d2.f.y = xs[b];
            ffma2(acc[0][b], p0.u, d2.u);
            ffma2(acc[1][b], p1.u, d2.u);
        }
    }

    float bias[4];
#pragma unroll
    for (int j = 0; j < 4; j++)
        bias[j] = bih[h0 + tx + 64 * j] + bhh[h0 + tx + 64 * j];

#pragma unroll
    for (int b = 0; b < 4; b++) {
        float* pr = g_pre + ((size_t)l * B_SZ + b0 + b) * DST + h0 + tx;
        U64F u0, u1; u0.u = acc[0][b]; u1.u = acc[1][b];
        pr[0]   = u0.f.x + bias[0];
        pr[64]  = u0.f.y + bias[1];
        pr[128] = u1.f.x + bias[2];
        pr[192] = u1.f.y + bias[3];
    }
}

// ---------------------------------------------------------------------------
// Kernel 2: recurrent scan. 8 clusters x 8 CTAs x 640 threads; 4 batches per
// cluster = 4 independent sync domains (hop hidden behind 3 batches' compute).
// Per-source mbarriers [batch][slot][src] (count=1): warp kw waits only on
// source-CTA kw. red[] double-buffered by step parity (2-step reuse, safe via
// cross-CTA chain). Phase named barriers alternate by step parity.
//   warps 0-15: compute (W in regs, broadcast LDS)
//   warps 16-19: tail for batch (warp-16); thread u owns rows u, u+32.
// ---------------------------------------------------------------------------
__global__ void __launch_bounds__(640, 1) __cluster_dims__(8, 1, 1)
k_rnn(const float* __restrict__ Whh) {
    __shared__ float hbuf[2][NB4 * DST];     // 16 KB exchange buffers
    __shared__ float red[2][NB4][64][9];     // 18 KB partials, step-parity buffered
    __shared__ __align__(8) unsigned long long barr[NB4][2][8]; // [b][slot][src]

    const int t    = threadIdx.x;
    const int warp = t >> 5;
    const int lane = t & 31;
    uint32_t rank;
    asm("mov.u32 %0, %%cluster_ctarank;" : "=r"(rank));
    const int cl = blockIdx.x >> 3;          // cluster id 0..7

    // compute-warp constants + register W
    const int rg  = warp & 1;
    const int kw  = warp >> 1;               // K slice / source CTA 0..7
    const int row = rg * 32 + lane;          // local row 0..63
    const int ks  = kw * 64;
    F4U w[16];
    if (t < 512) {
        const float4* wp = (const float4*)(Whh + (size_t)(rank * 64 + row) * DST + ks);
#pragma unroll
        for (int i = 0; i < 16; i++) w[i].f4 = wp[i];
    }

    // h_{-1} = 0 lives in parity buffer 1
    for (int i = t; i < NB4 * DST; i += 640) hbuf[1][i] = 0.f;

    uint32_t bar0 = smem_u32(&barr[0][0][0]);
    if (t == 0) {
        for (int i = 0; i < NB4 * 2 * 8; i++)
            asm volatile("mbarrier.init.shared.b64 [%0], %1;"
                         :: "r"(bar0 + 8u * i), "r"(1u) : "memory");
        asm volatile("fence.mbarrier_init.release.cluster;" ::: "memory");
    }
    __syncthreads();
    asm volatile("barrier.cluster.arrive.aligned;" ::: "memory");
    asm volatile("barrier.cluster.wait.aligned;" ::: "memory");

    const uint32_t hbase = smem_u32(&hbuf[0][0]);
    uint32_t peer_h[8];
#pragma unroll
    for (int p = 0; p < 8; p++)
        asm("mapa.shared::cluster.u32 %0, %1, %2;" : "=r"(peer_h[p]) : "r"(hbase), "r"(p));

    if (t < 512) {
        // ================= COMPUTE WARPS =================
        for (int l = 0; l < L_SEQ; l++) {
            const int prev = (l & 1) ^ 1;
            const int rbuf = l & 1;
            const uint32_t wslot = (uint32_t)((l - 1) & 1);
            const uint32_t wpar  = (uint32_t)(((l - 1) >> 1) & 1);
            const float* hbp = hbuf[prev];
            // my source's mbarrier offset within [b] group: (slot*8 + kw)
            const uint32_t srcoff = 8u * (wslot * 8u + (uint32_t)kw);

#pragma unroll
            for (int b = 0; b < NB4; b++) {
                if (l > 0)
                    mbar_wait_cluster(bar0 + (uint32_t)(b * 128) + srcoff, wpar);
                const float4* hp = (const float4*)(hbp + b * DST + ks);
                unsigned long long a0 = 0ull, a1 = 0ull;
#pragma unroll
                for (int i = 0; i < 16; i++) {
                    F4U hv; hv.f4 = hp[i];      // broadcast LDS
                    ffma2(a0, hv.u2.x, w[i].u2.x);
                    ffma2(a1, hv.u2.y, w[i].u2.y);
                }
                U64F u0, u1; u0.u = a0; u1.u = a1;
                red[rbuf][b][row][kw] = u0.f.x + u0.f.y + u1.f.x + u1.f.y;
                // phase barrier: id alternates by step parity (no phase slip)
                asm volatile("bar.arrive %0, 544;"
                             :: "r"(1 + b * 2 + (l & 1)) : "memory");
            }
        }
    } else {
        // ================= TAIL WARPS (one per batch) =================
        const int tb = warp - 16;               // my batch 0..3
        const int u  = lane;                    // rows u and u+32
        const size_t oi0 = (size_t)(cl * NB4 + tb) * DST + rank * 64 + u;
        const uint32_t po0 = (uint32_t)((tb * DST + (int)rank * 64 + u) * 4);

        for (int l = 0; l < L_SEQ; l++) {
            const int cur  = l & 1;
            const int rbuf = l & 1;
            float pv0 = __ldg(g_pre + (size_t)l * (B_SZ * DST) + oi0);
            float pv1 = __ldg(g_pre + (size_t)l * (B_SZ * DST) + oi0 + 32);

            asm volatile("bar.sync %0, 544;"
                         :: "r"(1 + tb * 2 + (l & 1)) : "memory");

            float s0 = pv0, s1 = pv1;
#pragma unroll
            for (int k2 = 0; k2 < 8; k2++) {
                s0 += red[rbuf][tb][u][k2];
                s1 += red[rbuf][tb][u + 32][k2];
            }
            float hv0 = tanhf(s0), hv1 = tanhf(s1);
            g_hs[(size_t)l * (B_SZ * DST) + oi0]      = hv0;
            g_hs[(size_t)l * (B_SZ * DST) + oi0 + 32] = hv1;

            if (l < L_SEQ - 1) {
                uint32_t off0 = (uint32_t)(cur * NB4 * DST * 4) + po0;
#pragma unroll
                for (int p = 0; p < 8; p++) {
                    asm volatile("st.shared::cluster.f32 [%0], %1;"
                                 :: "r"(peer_h[p] + off0), "f"(hv0) : "memory");
                    asm volatile("st.shared::cluster.f32 [%0], %1;"
                                 :: "r"(peer_h[p] + off0 + 128), "f"(hv1) : "memory");
                }
                // order this warp's 16 pushes before the arrives
                asm volatile("bar.sync %0, 32;" :: "r"(9 + tb) : "memory");
                if (u < 8) {
                    // arrive peer u's mbar[tb][cur][rank]
                    uint32_t local = bar0 + (uint32_t)(tb * 128)
                                   + 8u * ((uint32_t)cur * 8u + rank);
                    uint32_t ra;
                    asm("mapa.shared::cluster.u32 %0, %1, %2;"
                        : "=r"(ra) : "r"(local), "r"(u));
                    asm volatile("mbarrier.arrive.release.cluster.shared::cluster.b64 _, [%0];"
                                 :: "r"(ra) : "memory");
                }
            }
        }
    }

    // No CTA may exit while peers could still touch its smem.
    asm volatile("barrier.cluster.arrive.aligned;" ::: "memory");
    asm volatile("barrier.cluster.wait.aligned;" ::: "memory");
}

// ---------------------------------------------------------------------------
// Kernel 3: y[lb][o] = tanh(b_fc[o] + sum_k hs[lb][k] * W_fc[o][k])
// ---------------------------------------------------------------------------
#define OUT_SMEM ((128 * 132 + 128 * 68) * 4)

__global__ void __launch_bounds__(512) k_out(const float* __restrict__ Wfc,
                                             const float* __restrict__ bfc,
                                             float* __restrict__ y) {
    extern __shared__ float sm[];
    float* w_s = sm;               // [128 kk][132]
    float* a_s = sm + 128 * 132;   // [128 kk][68]

    const int t = threadIdx.x;
    const size_t base = (size_t)blockIdx.x * 64;
    const int tx  = t & 31;
    const int lb0 = (t >> 5) * 4;

    unsigned long long acc[2][4];
#pragma unroll
    for (int m = 0; m < 2; m++)
#pragma unroll
        for (int b = 0; b < 4; b++) acc[m][b] = 0ull;

    for (int kc = 0; kc < 4; kc++) {
        __syncthreads();
        for (int idx = t; idx < 128 * 128; idx += 512) {
            int kk = idx & 127, o = idx >> 7;
            w_s[kk * 132 + o] = Wfc[(size_t)o * DST + kc * 128 + kk];
        }
        for (int idx = t; idx < 64 * 128; idx += 512) {
            int kk = idx & 127, row = idx >> 7;
            a_s[kk * 68 + row] = g_hs[(base + row) * DST + kc * 128 + kk];
        }
        __syncthreads();

#pragma unroll 4
        for (int k = 0; k < 128; k++) {
            const float* wr = w_s + k * 132 + tx;
            U64F p0, p1;
            p0.f.x = wr[0];  p0.f.y = wr[32];
            p1.f.x = wr[64]; p1.f.y = wr[96];
            F4U av; av.f4 = *(const float4*)(a_s + k * 68 + lb0);
            float as4[4] = {av.f4.x, av.f4.y, av.f4.z, av.f4.w};
#pragma unroll
            for (int b = 0; b < 4; b++) {
                U64F d2; d2.f.x = as4[b]; d2.f.y = as4[b];
                ffma2(acc[0][b], p0.u, d2.u);
                ffma2(acc[1][b], p1.u, d2.u);
            }
        }
    }

    float bias[4];
#pragma unroll
    for (int j = 0; j < 4; j++) bias[j] = bfc[tx + 32 * j];

#pragma unroll
    for (int b = 0; b < 4; b++) {
        float* yp = y + (base + lb0 + b) * DIN + tx;
        U64F u0, u1; u0.u = acc[0][b]; u1.u = acc[1][b];
        yp[0]  = tanhf(u0.f.x + bias[0]);
        yp[32] = tanhf(u0.f.y + bias[1]);
        yp[64] = tanhf(u1.f.x + bias[2]);
        yp[96] = tanhf(u1.f.y + bias[3]);
    }
}

// ---------------------------------------------------------------------------
extern "C" void kernel_launch(void* const* d_in, const int* in_sizes, int n_in,
                              void* d_out, int out_size) {
    const float* x   = (const float*)d_in[0];
    const float* Wih = (const float*)d_in[1];
    const float* Whh = (const float*)d_in[2];
    const float* bih = (const float*)d_in[3];
    const float* bhh = (const float*)d_in[4];
    const float* Wfc = (const float*)d_in[5];
    const float* bfc = (const float*)d_in[6];
    float* y = (float*)d_out;

    cudaFuncSetAttribute(k_pre, cudaFuncAttributeMaxDynamicSharedMemorySize, PRE_SMEM);
    cudaFuncSetAttribute(k_out, cudaFuncAttributeMaxDynamicSharedMemorySize, OUT_SMEM);

    k_xT<<<dim3(L_SEQ / 32, (B_SZ * DIN) / 32), 256>>>(x);
    k_pre<<<dim3(L_SEQ, 2), 512, PRE_SMEM>>>(Wih, bih, bhh);
    k_rnn<<<64, 640>>>(Whh);
    k_out<<<(L_SEQ * B_SZ) / 64, 512, OUT_SMEM>>>(Wfc, bfc, y);
}